// round 15
// baseline (speedup 1.0000x reference)
#include <cuda_runtime.h>
#include <cuda_bf16.h>
#include <math.h>
#include <stdint.h>

// LCNECortexLSTM B=65536, D=H=256 — mma.sync (HMMA bf16) split-precision pipeline.
// R15: skewed warp-group pipeline. G0 = warps 0-3 (rows 0-63), G1 = warps 4-7
// (rows 64-127). Each phase: [G0 transform(p) | G1 MMA(p-1)]; barrier;
// [G0 MMA(p) | G1 transform(p)]. Tensor pipe fed in BOTH half-phases.
// Transform reads global directly (covered by other group's MMA); B is
// cp.async double-buffered with a full phase of prefetch cover.
// CTA tile 128x128, warp tile 64x32, __launch_bounds__(256,2) -> 2 CTAs/SM.
// D_fp32 = Ahi@Bhi + Ahi@Blo + Alo@Bhi.

#define BD 65536
#define HD 256
#define MT 128
#define NT 128
#define NTH 256

#define OFF_AHI 0
#define OFF_ALO 16384
#define OFF_BHI 32768
#define OFF_BLO 65536
#define OFF_SCALE 98304
#define OFF_SHIFT 99328
#define OFF_WP 100352
#define OFF_PS 101376
#define SMEM_REQ 102912

// weight images: [mat][hi/lo], transposed [N][K], chunked 4x(256 rows x 64 k),
// 128B rows with XOR-16B swizzle. mats: 0=Wx 1=Wh 2=Wf 3=WxWC 4=WxWi 5=WLC 6=Wo
__device__ __nv_bfloat16 g_Wimg[7][2][HD * HD];
__device__ float g_WxWi[HD * HD];
__device__ float g_WxWC[HD * HD];
__device__ float g_bxWi[HD];
__device__ float g_bxWC[HD];
__device__ float g_stats[6 * HD];
__device__ float g_scr1[(size_t)BD * HD];  // LC_raw
__device__ float g_scr2[(size_t)BD * HD];  // NE_raw

__device__ __forceinline__ float sigm(float x) { return 1.0f / (1.0f + expf(-x)); }
__device__ __forceinline__ float lky(float x) { return x > 0.0f ? x : 0.1f * x; }

__device__ __forceinline__ uint32_t smem_to_u32(const void* p) {
    uint32_t a;
    asm("{ .reg .u64 t; cvta.to.shared.u64 t, %1; cvt.u32.u64 %0, t; }" : "=r"(a) : "l"(p));
    return a;
}

__device__ __forceinline__ void ldsm_x4(uint32_t* r, uint32_t addr) {
    asm volatile("ldmatrix.sync.aligned.m8n8.x4.shared.b16 {%0,%1,%2,%3}, [%4];"
        : "=r"(r[0]), "=r"(r[1]), "=r"(r[2]), "=r"(r[3]) : "r"(addr));
}
__device__ __forceinline__ void ldsm_x2(uint32_t* r, uint32_t addr) {
    asm volatile("ldmatrix.sync.aligned.m8n8.x2.shared.b16 {%0,%1}, [%2];"
        : "=r"(r[0]), "=r"(r[1]) : "r"(addr));
}
__device__ __forceinline__ void mma_bf16(float* c, const uint32_t* a, const uint32_t* b) {
    asm("mma.sync.aligned.m16n8k16.row.col.f32.bf16.bf16.f32 "
        "{%0,%1,%2,%3}, {%4,%5,%6,%7}, {%8,%9}, {%0,%1,%2,%3};"
        : "+f"(c[0]), "+f"(c[1]), "+f"(c[2]), "+f"(c[3])
        : "r"(a[0]), "r"(a[1]), "r"(a[2]), "r"(a[3]), "r"(b[0]), "r"(b[1]));
}
__device__ __forceinline__ void cp16(uint32_t dst, const void* src) {
    asm volatile("cp.async.cg.shared.global [%0], [%1], 16;" :: "r"(dst), "l"(src));
}
#define CP_COMMIT asm volatile("cp.async.commit_group;" ::: "memory")
#define CP_WAIT0 asm volatile("cp.async.wait_group 0;" ::: "memory")

__device__ __forceinline__ uint32_t pack_split(float a, float b, uint32_t& lo) {
    __nv_bfloat162 h = __floats2bfloat162_rn(a, b);
    __nv_bfloat162 l = __floats2bfloat162_rn(a - __low2float(h), b - __high2float(h));
    lo = *reinterpret_cast<uint32_t*>(&l);
    return *reinterpret_cast<uint32_t*>(&h);
}

// ---------------- kernel body macros ----------------

#define GEMM_PROLOG                                                           \
    extern __shared__ char dsm_[];                                            \
    char* smem = (char*)(((uintptr_t)dsm_ + 1023) & ~(uintptr_t)1023);        \
    const int tid = threadIdx.x, wid = tid >> 5, lane = tid & 31;             \
    const int wm = wid >> 2, wn = wid & 3;                                    \
    const int grp = tid >> 7, ltid = tid & 127;                               \
    const int trow = grp * 64 + (ltid >> 1);   /* global-in-tile row owned */ \
    const int tk = (ltid & 1) * 32;            /* k-column base owned */      \
    const int row0 = blockIdx.x * MT;                                         \
    const int ncol0 = blockIdx.y * NT;                                        \
    const uint32_t su = smem_to_u32(smem);                                    \
    char* sAhi = smem + OFF_AHI; char* sAlo = smem + OFF_ALO;                 \
    const uint32_t uAhi = su + OFF_AHI, uAlo = su + OFF_ALO;                  \
    const uint32_t uBhi = su + OFF_BHI, uBlo = su + OFF_BLO;                  \
    float* sScale = (float*)(smem + OFF_SCALE);                               \
    float* sShift = (float*)(smem + OFF_SHIFT);                               \
    (void)sScale; (void)sShift; (void)sAlo; (void)trow; (void)tk;             \
    float acc[4][4][4];                                                       \
    _Pragma("unroll") for (int i_ = 0; i_ < 4; i_++)                          \
        _Pragma("unroll") for (int j_ = 0; j_ < 4; j_++)                      \
            _Pragma("unroll") for (int q_ = 0; q_ < 4; q_++)                  \
                acc[i_][j_][q_] = 0.0f;

// cp.async one pre-swizzled B half-chunk (16KB hi + 16KB lo) into buffer BP.
#define B_CPASYNC(WHI, WLO, CH, BP)                                           \
    {                                                                         \
        const char* bh_ = (const char*)((WHI) + (CH) * 16384 + ncol0 * 64);   \
        const char* bl_ = (const char*)((WLO) + (CH) * 16384 + ncol0 * 64);   \
        uint32_t db_ = (uint32_t)(BP) * 16384;                                \
        _Pragma("unroll") for (int i = 0; i < 4; i++) {                       \
            uint32_t o_ = (uint32_t)(i * NTH + tid) * 16;                     \
            cp16(uBhi + db_ + o_, bh_ + o_);                                  \
            cp16(uBlo + db_ + o_, bl_ + o_);                                  \
        }                                                                     \
        CP_COMMIT;                                                            \
    }

// MMA over this warp's 64x32 tile using B buffer BP. wm selects the M-half.
#define COMPUTE_CHUNK(BP)                                                     \
    _Pragma("unroll") for (int ks = 0; ks < 4; ks++) {                        \
        uint32_t ah[4][4], al[4][4];                                          \
        _Pragma("unroll") for (int mi = 0; mi < 4; mi++) {                    \
            int r = wm * 64 + mi * 16 + (lane & 15);                          \
            int kb = ks * 32 + ((lane & 16) ? 16 : 0);                        \
            uint32_t sw = (uint32_t)r * 128 + (kb ^ ((r & 7) << 4));          \
            ldsm_x4(ah[mi], uAhi + sw);                                       \
            ldsm_x4(al[mi], uAlo + sw);                                       \
        }                                                                     \
        _Pragma("unroll") for (int ni = 0; ni < 4; ni++) {                    \
            int l = lane & 15;                                                \
            int rn = wn * 32 + ni * 8 + (l & 7);                              \
            int kb = ks * 32 + ((l & 8) ? 16 : 0);                            \
            uint32_t sw = (uint32_t)(BP) * 16384 + (uint32_t)rn * 128 +       \
                          (uint32_t)(kb ^ ((rn & 7) << 4));                   \
            uint32_t bh2[2], bl2[2];                                          \
            ldsm_x2(bh2, uBhi + sw);                                          \
            ldsm_x2(bl2, uBlo + sw);                                          \
            _Pragma("unroll") for (int mi = 0; mi < 4; mi++)                  \
                mma_bf16(acc[mi][ni], ah[mi], bh2);                           \
            _Pragma("unroll") for (int mi = 0; mi < 4; mi++)                  \
                mma_bf16(acc[mi][ni], ah[mi], bl2);                           \
            _Pragma("unroll") for (int mi = 0; mi < 4; mi++)                  \
                mma_bf16(acc[mi][ni], al[mi], bh2);                           \
        }                                                                     \
    }

#define SPLIT_STORE(av, r, cc)                                                \
    {                                                                         \
        uint2 h2, l2;                                                         \
        h2.x = pack_split((av).x, (av).y, l2.x);                              \
        h2.y = pack_split((av).z, (av).w, l2.y);                              \
        uint32_t off = (uint32_t)(r) * 128 + (((cc) * 2) ^ (((r) & 7) << 4)); \
        *(uint2*)(sAhi + off) = h2;                                           \
        *(uint2*)(sAlo + off) = l2;                                           \
    }

// group transform: this thread owns row trow, 32 cols at tk (8 float4s),
// reads global directly (latency hidden behind other group's MMA).
#define A_TRANS_PLAIN(SRC, KB)                                                \
    {                                                                         \
        const float* gs_ = (SRC) + (size_t)(row0 + trow) * HD + (KB) + tk;    \
        _Pragma("unroll") for (int h8 = 0; h8 < 2; h8++) {                    \
            float4 av_[4];                                                    \
            _Pragma("unroll") for (int q = 0; q < 4; q++)                     \
                av_[q] = *(const float4*)(gs_ + h8 * 16 + q * 4);             \
            _Pragma("unroll") for (int q = 0; q < 4; q++)                     \
                SPLIT_STORE(av_[q], trow, tk + h8 * 16 + q * 4);              \
        }                                                                     \
    }

#define A_TRANS_BN(SRC, OUT, KB)                                              \
    {                                                                         \
        const float* gs_ = (SRC) + (size_t)(row0 + trow) * HD + (KB) + tk;    \
        float* go_ = (OUT) + (size_t)(row0 + trow) * HD + (KB) + tk;          \
        _Pragma("unroll") for (int h8 = 0; h8 < 2; h8++) {                    \
            float4 av_[4];                                                    \
            _Pragma("unroll") for (int q = 0; q < 4; q++)                     \
                av_[q] = *(const float4*)(gs_ + h8 * 16 + q * 4);             \
            _Pragma("unroll") for (int q = 0; q < 4; q++) {                   \
                int kc_ = tk + h8 * 16 + q * 4;                               \
                float4 sc_ = *(float4*)&sScale[(KB) + kc_];                   \
                float4 sh_ = *(float4*)&sShift[(KB) + kc_];                   \
                av_[q].x = lky(fmaf(av_[q].x, sc_.x, sh_.x));                 \
                av_[q].y = lky(fmaf(av_[q].y, sc_.y, sh_.y));                 \
                av_[q].z = lky(fmaf(av_[q].z, sc_.z, sh_.z));                 \
                av_[q].w = lky(fmaf(av_[q].w, sc_.w, sh_.w));                 \
                *(float4*)(go_ + h8 * 16 + q * 4) = av_[q];                   \
                SPLIT_STORE(av_[q], trow, kc_);                               \
            }                                                                 \
        }                                                                     \
    }

#define A_TRANS_TP(SRC, OUT, LCP, NEP, KB)                                    \
    {                                                                         \
        size_t gb_ = (size_t)(row0 + trow) * HD + (KB) + tk;                  \
        const float* gs_ = (SRC) + gb_;                                       \
        _Pragma("unroll") for (int h8 = 0; h8 < 2; h8++) {                    \
            float4 av_[4];                                                    \
            _Pragma("unroll") for (int q = 0; q < 4; q++)                     \
                av_[q] = *(const float4*)(gs_ + h8 * 16 + q * 4);             \
            _Pragma("unroll") for (int q = 0; q < 4; q++) {                   \
                int kc_ = tk + h8 * 16 + q * 4;                               \
                float4 sc_ = *(float4*)&sScale[(KB) + kc_];                   \
                float4 sh_ = *(float4*)&sShift[(KB) + kc_];                   \
                float4 wp_ = *(float4*)&sWP[(KB) + kc_];                      \
                av_[q].x = lky(fmaf(av_[q].x, sc_.x, sh_.x));                 \
                av_[q].y = lky(fmaf(av_[q].y, sc_.y, sh_.y));                 \
                av_[q].z = lky(fmaf(av_[q].z, sc_.z, sh_.z));                 \
                av_[q].w = lky(fmaf(av_[q].w, sc_.w, sh_.w));                 \
                *(float4*)((OUT) + gb_ + h8 * 16 + q * 4) = av_[q];           \
                float4 lv_ = *(const float4*)((LCP) + gb_ + h8 * 16 + q * 4); \
                float4 nv_ = *(const float4*)((NEP) + gb_ + h8 * 16 + q * 4); \
                pval = fmaf(av_[q].x + lv_.x + nv_.x, wp_.x, pval);           \
                pval = fmaf(av_[q].y + lv_.y + nv_.y, wp_.y, pval);           \
                pval = fmaf(av_[q].z + lv_.z + nv_.z, wp_.z, pval);           \
                pval = fmaf(av_[q].w + lv_.w + nv_.w, wp_.w, pval);           \
                SPLIT_STORE(av_[q], trow, kc_);                               \
            }                                                                 \
        }                                                                     \
    }

// skewed phase loop: C chunks. TRANSFORM(c) and MMA via COMPUTE_CHUNK.
// SELB(c) must expand to {const __nv_bfloat16 *wh_, *wl_; int wch_;} setup.
#define PIPELINE(C, SELB, TRANSFORM)                                          \
    {                                                                         \
        { SELB(0); B_CPASYNC(wh_, wl_, wch_, 0); }                            \
        _Pragma("unroll 1")                                                   \
        for (int p = 0; p <= (C); p++) {                                      \
            __syncthreads();                                                  \
            if (grp == 0) {                                                   \
                if (p < (C)) { TRANSFORM(p); }                                \
            } else {                                                          \
                if (p >= 1) { COMPUTE_CHUNK((p - 1) & 1); }                   \
            }                                                                 \
            CP_WAIT0;                                                         \
            __syncthreads();                                                  \
            if (p + 1 < (C)) { SELB(p + 1); B_CPASYNC(wh_, wl_, wch_, (p + 1) & 1); } \
            if (grp == 0) {                                                   \
                if (p < (C)) { COMPUTE_CHUNK(p & 1); }                        \
            } else {                                                          \
                if (p < (C)) { TRANSFORM(p); }                                \
            }                                                                 \
        }                                                                     \
    }

// epilogue iteration: rr = global row, cb = global column (pair base)
#define EPI_BEGIN                                                             \
    _Pragma("unroll") for (int mi = 0; mi < 4; mi++) {                        \
        _Pragma("unroll") for (int h = 0; h < 2; h++) {                       \
            const int rr = row0 + wm * 64 + mi * 16 + (lane >> 2) + h * 8;    \
            _Pragma("unroll") for (int ni = 0; ni < 4; ni++) {                \
                const int cb = ncol0 + wn * 32 + ni * 8 + (lane & 3) * 2;     \
                float vx = acc[mi][ni][h * 2], vy = acc[mi][ni][h * 2 + 1];   \
                (void)cb;

#define EPI_END_STORE(OUT)                                                    \
                *(float2*)((OUT) + (size_t)rr * HD + cb) = make_float2(vx, vy); \
            } } }

#define EPI_END_ACC                                                           \
                acc[mi][ni][h * 2] = vx; acc[mi][ni][h * 2 + 1] = vy;         \
            } } }

#define STATS_DECL                                                            \
    float ssum[4][2], ssq[4][2];                                              \
    _Pragma("unroll") for (int i_ = 0; i_ < 4; i_++) {                        \
        ssum[i_][0] = ssum[i_][1] = 0.0f; ssq[i_][0] = ssq[i_][1] = 0.0f; }

#define STATS_ACC                                                             \
    ssum[ni][0] += vx; ssq[ni][0] += vx * vx;                                 \
    ssum[ni][1] += vy; ssq[ni][1] += vy * vy;

#define STATS_REDUCE(SIDX)                                                    \
    _Pragma("unroll") for (int ni = 0; ni < 4; ni++) {                        \
        _Pragma("unroll") for (int c2 = 0; c2 < 2; c2++) {                    \
            float s_ = ssum[ni][c2], q_ = ssq[ni][c2];                        \
            s_ += __shfl_xor_sync(~0u, s_, 4);  q_ += __shfl_xor_sync(~0u, q_, 4);  \
            s_ += __shfl_xor_sync(~0u, s_, 8);  q_ += __shfl_xor_sync(~0u, q_, 8);  \
            s_ += __shfl_xor_sync(~0u, s_, 16); q_ += __shfl_xor_sync(~0u, q_, 16); \
            if (lane < 4) {                                                   \
                int col = ncol0 + wn * 32 + ni * 8 + lane * 2 + c2;           \
                atomicAdd(&g_stats[(SIDX) * HD + col], s_);                   \
                atomicAdd(&g_stats[((SIDX) + 1) * HD + col], q_);             \
            } } }

#define BN_PREP(SIDX, G, B)                                                   \
    {                                                                         \
        float m_ = g_stats[(SIDX) * HD + tid] * (1.0f / (float)BD);           \
        float e2_ = g_stats[((SIDX) + 1) * HD + tid] * (1.0f / (float)BD);    \
        float rs_ = rsqrtf(e2_ - m_ * m_ + 1e-5f);                            \
        float sc_ = rs_ * (G)[tid];                                           \
        sScale[tid] = sc_;                                                    \
        sShift[tid] = (B)[tid] - m_ * sc_;                                    \
    }

#define BIAS4(DST, SRCP)                                                      \
    float2 DST[4];                                                            \
    _Pragma("unroll") for (int i_ = 0; i_ < 4; i_++)                          \
        DST[i_] = *(const float2*)((SRCP) + ncol0 + wn * 32 + i_ * 8 + (lane & 3) * 2);

// ---------------- prep kernels ----------------

__global__ void __launch_bounds__(NTH) k0_prep(
    const float* __restrict__ Wx, const float* __restrict__ bx,
    const float* __restrict__ Wi, const float* __restrict__ bi,
    const float* __restrict__ WC, const float* __restrict__ bC) {
    int h = threadIdx.x;
    if (blockIdx.x < HD) {
        __shared__ float sA[HD];
        sA[h] = Wx[blockIdx.x * HD + h];
        __syncthreads();
        float aI = 0.0f, aC = 0.0f;
#pragma unroll 4
        for (int k = 0; k < HD; k++) {
            float a = sA[k];
            aI = fmaf(a, Wi[k * HD + h], aI);
            aC = fmaf(a, WC[k * HD + h], aC);
        }
        g_WxWi[blockIdx.x * HD + h] = aI;
        g_WxWC[blockIdx.x * HD + h] = aC;
    } else {
        float aI = bi[h], aC = bC[h];
        for (int k = 0; k < HD; k++) {
            float a = bx[k];
            aI = fmaf(a, Wi[k * HD + h], aI);
            aC = fmaf(a, WC[k * HD + h], aC);
        }
        g_bxWi[h] = aI;
        g_bxWC[h] = aC;
#pragma unroll
        for (int s = 0; s < 6; s++) g_stats[s * HD + h] = 0.0f;
    }
}

// weights -> transposed [N][K] bf16 hi/lo, chunked by K=64, XOR-swizzled 128B rows
__global__ void __launch_bounds__(NTH) kW(
    const float* __restrict__ Wx, const float* __restrict__ Wh,
    const float* __restrict__ Wf, const float* __restrict__ WLC,
    const float* __restrict__ Wo) {
    int k = blockIdx.x, m = blockIdx.y, n = threadIdx.x;
    const float* src;
    switch (m) {
        case 0: src = Wx; break;
        case 1: src = Wh; break;
        case 2: src = Wf; break;
        case 3: src = g_WxWC; break;
        case 4: src = g_WxWi; break;
        case 5: src = WLC; break;
        default: src = Wo; break;
    }
    float val = src[k * HD + n];
    __nv_bfloat16 h = __float2bfloat16(val);
    __nv_bfloat16 l = __float2bfloat16(val - __bfloat162float(h));
    int chunk = k >> 6, kk = k & 63;
    uint32_t off = (uint32_t)chunk * 32768 + (uint32_t)n * 128 + ((kk * 2) ^ ((n & 7) << 4));
    *(__nv_bfloat16*)((char*)g_Wimg[m][0] + off) = h;
    *(__nv_bfloat16*)((char*)g_Wimg[m][1] + off) = l;
}

// ---------------- GEMM kernels ----------------

// k1a: LC_raw = X@Wx + pLC@Wh + (bx+bh) -> g_scr1; stats0 (8 chunks)
#define SELB_1A(c) const __nv_bfloat16* wh_ = g_Wimg[(c) < 4 ? 0 : 1][0];     \
                   const __nv_bfloat16* wl_ = g_Wimg[(c) < 4 ? 0 : 1][1];     \
                   int wch_ = (c) & 3
#define TR_1A(c) { const float* s_ = ((c) < 4) ? X : pLC; A_TRANS_PLAIN(s_, ((c) & 3) * 64); }
__global__ void __launch_bounds__(NTH, 2) k1a(
    const float* __restrict__ X, const float* __restrict__ pLC,
    const float* __restrict__ bx, const float* __restrict__ bh_) {
    GEMM_PROLOG;
    PIPELINE(8, SELB_1A, TR_1A);
    BIAS4(b1, bx); BIAS4(b2, bh_);
    STATS_DECL;
    EPI_BEGIN;
    vx += b1[ni].x + b2[ni].x;
    vy += b1[ni].y + b2[ni].y;
    STATS_ACC;
    EPI_END_STORE(g_scr1);
    STATS_REDUCE(0);
}

// k1b: base = sigmoid(pC@Wf+bf)*cell + X@WxWC + bxWC -> sec2; sigmoid mid-
// transform applied right after each warp's MMA of chunk 3 (per-warp registers).
#define SELB_1B(c) const __nv_bfloat16* wh_ = g_Wimg[(c) < 4 ? 2 : 3][0];     \
                   const __nv_bfloat16* wl_ = g_Wimg[(c) < 4 ? 2 : 3][1];     \
                   int wch_ = (c) & 3
#define TR_1B(c) { const float* s_ = ((c) < 4) ? pC : X; A_TRANS_PLAIN(s_, ((c) & 3) * 64); }
#define MID_1B                                                                \
    {                                                                         \
        BIAS4(bfv, bf_);                                                      \
        EPI_BEGIN;                                                            \
        float2 cv = *(const float2*)(cell + (size_t)rr * HD + cb);            \
        vx = sigm(vx + bfv[ni].x) * cv.x;                                     \
        vy = sigm(vy + bfv[ni].y) * cv.y;                                     \
        EPI_END_ACC;                                                          \
    }
__global__ void __launch_bounds__(NTH, 2) k1b(
    const float* __restrict__ pC, const float* __restrict__ X,
    const float* __restrict__ bf_, const float* __restrict__ cell, float* out) {
    GEMM_PROLOG;
    {
        { SELB_1B(0); B_CPASYNC(wh_, wl_, wch_, 0); }
#pragma unroll 1
        for (int p = 0; p <= 8; p++) {
            __syncthreads();
            if (grp == 0) {
                if (p < 8) { TR_1B(p); }
            } else {
                if (p >= 1) {
                    COMPUTE_CHUNK((p - 1) & 1);
                    if (p - 1 == 3) MID_1B;
                }
            }
            CP_WAIT0;
            __syncthreads();
            if (p + 1 < 8) { SELB_1B(p + 1); B_CPASYNC(wh_, wl_, wch_, (p + 1) & 1); }
            if (grp == 0) {
                if (p < 8) {
                    COMPUTE_CHUNK(p & 1);
                    if (p == 3) MID_1B;
                }
            } else {
                if (p < 8) { TR_1B(p); }
            }
        }
    }
    BIAS4(bb, g_bxWC);
    EPI_BEGIN;
    vx += bb[ni].x;
    vy += bb[ni].y;
    EPI_END_STORE(out);
}

// k1c: igate = sigmoid(X@WxWi + bxWi) -> sec3 (4 chunks)
#define SELB_1C(c) const __nv_bfloat16* wh_ = g_Wimg[4][0];                   \
                   const __nv_bfloat16* wl_ = g_Wimg[4][1];                   \
                   int wch_ = (c)
#define TR_1C(c) A_TRANS_PLAIN(X, (c) * 64)
__global__ void __launch_bounds__(NTH, 2) k1c(const float* __restrict__ X, float* out) {
    GEMM_PROLOG;
    PIPELINE(4, SELB_1C, TR_1C);
    BIAS4(bb, g_bxWi);
    EPI_BEGIN;
    vx = sigm(vx + bb[ni].x);
    vy = sigm(vy + bb[ni].y);
    EPI_END_STORE(out);
}

// k2: LC_t = leaky(bn1(g_scr1)) -> sec0; NE_raw = LC_t@WLC + bLC -> g_scr2; stats2
#define SELB_K2(c) const __nv_bfloat16* wh_ = g_Wimg[5][0];                   \
                   const __nv_bfloat16* wl_ = g_Wimg[5][1];                   \
                   int wch_ = (c)
#define TR_K2(c) A_TRANS_BN(g_scr1, out_lct, (c) * 64)
__global__ void __launch_bounds__(NTH, 2) k2(
    float* out_lct, const float* __restrict__ bLC,
    const float* __restrict__ g1, const float* __restrict__ be1) {
    GEMM_PROLOG;
    BN_PREP(0, g1, be1);
    PIPELINE(4, SELB_K2, TR_K2);
    BIAS4(bb, bLC);
    STATS_DECL;
    EPI_BEGIN;
    vx += bb[ni].x;
    vy += bb[ni].y;
    STATS_ACC;
    EPI_END_STORE(g_scr2);
    STATS_REDUCE(2);
}

// k3: NE_t = leaky(bn2(g_scr2)) -> sec1; new_cell = base + ig*0.1*(NE_t@WLC+bLC) -> sec4; stats4
#define TR_K3(c) A_TRANS_BN(g_scr2, out_net, (c) * 64)
__global__ void __launch_bounds__(NTH, 2) k3(
    float* out_nc, float* out_net, const float* __restrict__ bLC,
    const float* __restrict__ base, const float* __restrict__ ig,
    const float* __restrict__ g2, const float* __restrict__ be2) {
    GEMM_PROLOG;
    BN_PREP(2, g2, be2);
    PIPELINE(4, SELB_K2, TR_K3);
    BIAS4(bb, bLC);
    STATS_DECL;
    EPI_BEGIN;
    float2 bv = *(const float2*)(base + (size_t)rr * HD + cb);
    float2 iv = *(const float2*)(ig + (size_t)rr * HD + cb);
    vx = fmaf(iv.x * 0.1f, vx + bb[ni].x, bv.x);
    vy = fmaf(iv.y * 0.1f, vy + bb[ni].y, bv.y);
    STATS_ACC;
    EPI_END_STORE(out_nc);
    STATS_REDUCE(4);
}

// k4: C_t = leaky(bn3(sec4)) -> sec2; p = (LC_t+C_t+NE_t)@WP;
//     Pupil = sigmoid(C_t@Wo+bo)*(p+bP) -> sec3
#define SELB_K4(c) const __nv_bfloat16* wh_ = g_Wimg[6][0];                   \
                   const __nv_bfloat16* wl_ = g_Wimg[6][1];                   \
                   int wch_ = (c)
#define TR_K4(c) A_TRANS_TP(ncell, out_ct, lct, net, (c) * 64)
__global__ void __launch_bounds__(NTH, 2) k4(
    const float* __restrict__ ncell, float* out_ct,
    const float* __restrict__ lct, const float* __restrict__ net,
    const float* __restrict__ bo, const float* __restrict__ WP,
    const float* __restrict__ bP, const float* __restrict__ g3,
    const float* __restrict__ be3, float* out_pupil) {
    GEMM_PROLOG;
    BN_PREP(4, g3, be3);
    float* sWP = (float*)(smem + OFF_WP);
    float* p_s = (float*)(smem + OFF_PS);
    sWP[tid] = WP[tid];
    if (tid < MT) p_s[tid] = 0.0f;
    float pval = 0.0f;
    PIPELINE(4, SELB_K4, TR_K4);
    atomicAdd(&p_s[trow], pval);
    __syncthreads();
    float bP0 = bP[0];
    BIAS4(bb, bo);
    EPI_BEGIN;
    float pr = p_s[rr - row0] + bP0;
    vx = sigm(vx + bb[ni].x) * pr;
    vy = sigm(vy + bb[ni].y) * pr;
    EPI_END_STORE(out_pupil);
}

// ---------------- launch ----------------

extern "C" void kernel_launch(void* const* d_in, const int* in_sizes, int n_in,
                              void* d_out, int out_size) {
    (void)in_sizes; (void)n_in; (void)out_size;
    const float* X    = (const float*)d_in[0];
    const float* pLC  = (const float*)d_in[1];
    const float* pC   = (const float*)d_in[2];
    const float* cell = (const float*)d_in[3];
    const float* Wx = (const float*)d_in[4];   const float* bx = (const float*)d_in[5];
    const float* Wh = (const float*)d_in[6];   const float* bh = (const float*)d_in[7];
    const float* WLC = (const float*)d_in[8];  const float* bLC = (const float*)d_in[9];
    const float* WC = (const float*)d_in[10];  const float* bC = (const float*)d_in[11];
    const float* WP = (const float*)d_in[12];  const float* bP = (const float*)d_in[13];
    const float* Wf = (const float*)d_in[14];  const float* bf = (const float*)d_in[15];
    const float* Wi = (const float*)d_in[16];  const float* bi = (const float*)d_in[17];
    const float* Wo = (const float*)d_in[18];  const float* bo = (const float*)d_in[19];
    const float* g1 = (const float*)d_in[20];  const float* be1 = (const float*)d_in[21];
    const float* g2 = (const float*)d_in[22];  const float* be2 = (const float*)d_in[23];
    const float* g3 = (const float*)d_in[24];  const float* be3 = (const float*)d_in[25];

    float* o = (float*)d_out;
    const size_t SEC = (size_t)BD * HD;
    float* sLC = o;            // LC_t   (written by k2)
    float* sNE = o + SEC;      // NE_t   (written by k3)
    float* sCT = o + 2 * SEC;  // C_t    (base until k3 consumes it; k4 writes C_t)
    float* sPU = o + 3 * SEC;  // Pupil  (igate until k3; k4 writes Pupil)
    float* sNC = o + 4 * SEC;  // new_cell (written by k3)

    // idempotent; called every time (no static guards per harness contract)
    cudaFuncSetAttribute(k1a, cudaFuncAttributeMaxDynamicSharedMemorySize, SMEM_REQ);
    cudaFuncSetAttribute(k1b, cudaFuncAttributeMaxDynamicSharedMemorySize, SMEM_REQ);
    cudaFuncSetAttribute(k1c, cudaFuncAttributeMaxDynamicSharedMemorySize, SMEM_REQ);
    cudaFuncSetAttribute(k2, cudaFuncAttributeMaxDynamicSharedMemorySize, SMEM_REQ);
    cudaFuncSetAttribute(k3, cudaFuncAttributeMaxDynamicSharedMemorySize, SMEM_REQ);
    cudaFuncSetAttribute(k4, cudaFuncAttributeMaxDynamicSharedMemorySize, SMEM_REQ);

    dim3 blk(NTH);
    dim3 grd(BD / MT, HD / NT);

    k0_prep<<<HD + 1, NTH>>>(Wx, bx, Wi, bi, WC, bC);
    kW<<<dim3(HD, 7), NTH>>>(Wx, Wh, Wf, WLC, Wo);
    k1a<<<grd, blk, SMEM_REQ>>>(X, pLC, bx, bh);
    k1b<<<grd, blk, SMEM_REQ>>>(pC, X, bf, cell, sCT);
    k1c<<<grd, blk, SMEM_REQ>>>(X, sPU);
    k2<<<grd, blk, SMEM_REQ>>>(sLC, bLC, g1, be1);
    k3<<<grd, blk, SMEM_REQ>>>(sNC, sNE, bLC, sCT, sPU, g2, be2);
    k4<<<grd, blk, SMEM_REQ>>>(sNC, sCT, sLC, sNE, bo, WP, bP, g3, be3, sPU);
}

// round 16
// speedup vs baseline: 1.0466x; 1.0466x over previous
#include <cuda_runtime.h>
#include <cuda_bf16.h>
#include <math.h>
#include <stdint.h>

// LCNECortexLSTM B=65536, D=H=256 — mma.sync (HMMA bf16) split-precision pipeline.
// R16 = R14 base + pre-split activation images. kA converts X/pLC/pC to bf16
// hi/lo images in swizzled tile layout; k1a/k1b/k1c become lean MMA pipelines
// (A double-buffered cp.async direct, B single, 2 barriers/chunk, no transform).
// k2/k3/k4 keep the R14 staged-transform path (BN depends on runtime stats).
// D_fp32 = Ahi@Bhi + Ahi@Blo + Alo@Bhi.

#define BD 65536
#define HD 256
#define MT 128
#define NT 128
#define NTH 256

// k2/3/4 layout: RAW 0(32K), AHI 32768(16K), ALO 49152(16K), BHI 65536, BLO 81920
// k1 layout:     A0hi 0, A0lo 16384, A1hi 32768, A1lo 49152, BHI 65536, BLO 81920
#define OFF_RAW 0
#define OFF_AHI 32768
#define OFF_ALO 49152
#define OFF_BHI 65536
#define OFF_BLO 81920
#define OFF_SCALE 98304
#define OFF_SHIFT 99328
#define OFF_WP 100352
#define OFF_PS 101376
#define SMEM_REQ 102912

// weight images: [mat][hi/lo], transposed [N][K], chunked 4x(256 rows x 64 k),
// 128B rows with XOR-16B swizzle. mats: 0=Wx 1=Wh 2=Wf 3=WxWC 4=WxWi 5=WLC 6=Wo
__device__ __nv_bfloat16 g_Wimg[7][2][HD * HD];
// activation images: [mat 0=X 1=pLC 2=pC][hi/lo], tiled (rowtile 128 x chunk 64)
// blocks of 8192 elems, rows 128B swizzled exactly like the A smem tiles.
__device__ __nv_bfloat16 g_Aimg[3][2][(size_t)BD * HD];
__device__ float g_WxWi[HD * HD];
__device__ float g_WxWC[HD * HD];
__device__ float g_bxWi[HD];
__device__ float g_bxWC[HD];
__device__ float g_stats[6 * HD];
__device__ float g_scr1[(size_t)BD * HD];  // LC_raw
__device__ float g_scr2[(size_t)BD * HD];  // NE_raw

__device__ __forceinline__ float sigm(float x) { return 1.0f / (1.0f + expf(-x)); }
__device__ __forceinline__ float lky(float x) { return x > 0.0f ? x : 0.1f * x; }

__device__ __forceinline__ uint32_t smem_to_u32(const void* p) {
    uint32_t a;
    asm("{ .reg .u64 t; cvta.to.shared.u64 t, %1; cvt.u32.u64 %0, t; }" : "=r"(a) : "l"(p));
    return a;
}

__device__ __forceinline__ void ldsm_x4(uint32_t* r, uint32_t addr) {
    asm volatile("ldmatrix.sync.aligned.m8n8.x4.shared.b16 {%0,%1,%2,%3}, [%4];"
        : "=r"(r[0]), "=r"(r[1]), "=r"(r[2]), "=r"(r[3]) : "r"(addr));
}
__device__ __forceinline__ void ldsm_x2(uint32_t* r, uint32_t addr) {
    asm volatile("ldmatrix.sync.aligned.m8n8.x2.shared.b16 {%0,%1}, [%2];"
        : "=r"(r[0]), "=r"(r[1]) : "r"(addr));
}
__device__ __forceinline__ void mma_bf16(float* c, const uint32_t* a, const uint32_t* b) {
    asm("mma.sync.aligned.m16n8k16.row.col.f32.bf16.bf16.f32 "
        "{%0,%1,%2,%3}, {%4,%5,%6,%7}, {%8,%9}, {%0,%1,%2,%3};"
        : "+f"(c[0]), "+f"(c[1]), "+f"(c[2]), "+f"(c[3])
        : "r"(a[0]), "r"(a[1]), "r"(a[2]), "r"(a[3]), "r"(b[0]), "r"(b[1]));
}
__device__ __forceinline__ void cp16(uint32_t dst, const void* src) {
    asm volatile("cp.async.cg.shared.global [%0], [%1], 16;" :: "r"(dst), "l"(src));
}
#define CP_COMMIT asm volatile("cp.async.commit_group;" ::: "memory")

__device__ __forceinline__ uint32_t pack_split(float a, float b, uint32_t& lo) {
    __nv_bfloat162 h = __floats2bfloat162_rn(a, b);
    __nv_bfloat162 l = __floats2bfloat162_rn(a - __low2float(h), b - __high2float(h));
    lo = *reinterpret_cast<uint32_t*>(&l);
    return *reinterpret_cast<uint32_t*>(&h);
}

// ---------------- kernel body macros ----------------

#define GEMM_PROLOG                                                           \
    extern __shared__ char dsm_[];                                            \
    char* smem = (char*)(((uintptr_t)dsm_ + 1023) & ~(uintptr_t)1023);        \
    const int tid = threadIdx.x, wid = tid >> 5, lane = tid & 31;             \
    const int wm = wid & 1, wn = wid >> 1;                                    \
    const int row0 = blockIdx.x * MT;                                         \
    const int ncol0 = blockIdx.y * NT;                                        \
    const uint32_t su = smem_to_u32(smem);                                    \
    char* sRAW = smem + OFF_RAW;                                              \
    char* sAhi = smem + OFF_AHI; char* sAlo = smem + OFF_ALO;                 \
    const uint32_t uBhi = su + OFF_BHI, uBlo = su + OFF_BLO;                  \
    float* sScale = (float*)(smem + OFF_SCALE);                               \
    float* sShift = (float*)(smem + OFF_SHIFT);                               \
    (void)sScale; (void)sShift; (void)sRAW; (void)sAhi; (void)sAlo;           \
    float acc[4][4][4];                                                       \
    _Pragma("unroll") for (int i_ = 0; i_ < 4; i_++)                          \
        _Pragma("unroll") for (int j_ = 0; j_ < 4; j_++)                      \
            _Pragma("unroll") for (int q_ = 0; q_ < 4; q_++)                  \
                acc[i_][j_][q_] = 0.0f;

// cp.async one raw fp32 A chunk (128 rows x 64 cols) into sRAW; commits a group.
#define A_CPASYNC(SRC, KB)                                                    \
    {                                                                         \
        const int pr_ = tid >> 4, ps_ = (tid & 15) * 16;                      \
        _Pragma("unroll") for (int ii = 0; ii < 8; ii++) {                    \
            int r_ = pr_ + ii * 16;                                           \
            cp16(su + OFF_RAW + (uint32_t)r_ * 256 + ps_,                     \
                 (const char*)((SRC) + (size_t)(row0 + r_) * HD + (KB)) + ps_); \
        }                                                                     \
        CP_COMMIT;                                                            \
    }

// cp.async one pre-split A image block (16KB hi + 16KB lo) into A buffer P; commits.
#define A2_CPASYNC(IMGH, IMGL, CC, P)                                         \
    {                                                                         \
        const char* ah_ = (const char*)((IMGH) + ((size_t)(blockIdx.x * 4 + (CC))) * 8192); \
        const char* al_ = (const char*)((IMGL) + ((size_t)(blockIdx.x * 4 + (CC))) * 8192); \
        uint32_t d_ = su + (uint32_t)(P) * 32768;                             \
        _Pragma("unroll") for (int i = 0; i < 4; i++) {                       \
            uint32_t o_ = (uint32_t)(i * NTH + tid) * 16;                     \
            cp16(d_ + o_, ah_ + o_);                                          \
            cp16(d_ + 16384 + o_, al_ + o_);                                  \
        }                                                                     \
        CP_COMMIT;                                                            \
    }

// cp.async one pre-swizzled B half-chunk (16KB hi + 16KB lo); commits a group.
#define B_CPASYNC(WHI, WLO, CH)                                               \
    {                                                                         \
        const char* bh_ = (const char*)((WHI) + (CH) * 16384 + ncol0 * 64);   \
        const char* bl_ = (const char*)((WLO) + (CH) * 16384 + ncol0 * 64);   \
        _Pragma("unroll") for (int i = 0; i < 4; i++) {                       \
            uint32_t o_ = (uint32_t)(i * NTH + tid) * 16;                     \
            cp16(uBhi + o_, bh_ + o_);                                        \
            cp16(uBlo + o_, bl_ + o_);                                        \
        }                                                                     \
        CP_COMMIT;                                                            \
    }

#define PIPE_WAIT_SYNC                                                        \
    asm volatile("cp.async.wait_group 0;" ::: "memory");                      \
    __syncthreads();

// AB = byte offset of A-hi buffer from su (lo at +16384). B fixed buffers.
#define COMPUTE_CHUNK(AB)                                                     \
    _Pragma("unroll") for (int ks = 0; ks < 4; ks++) {                        \
        uint32_t ah[4][4], al[4][4];                                          \
        _Pragma("unroll") for (int mi = 0; mi < 4; mi++) {                    \
            int r = wm * 64 + mi * 16 + (lane & 15);                          \
            int kb = ks * 32 + ((lane & 16) ? 16 : 0);                        \
            uint32_t sw = (uint32_t)r * 128 + (kb ^ ((r & 7) << 4));          \
            ldsm_x4(ah[mi], su + (AB) + sw);                                  \
            ldsm_x4(al[mi], su + (AB) + 16384 + sw);                          \
        }                                                                     \
        _Pragma("unroll") for (int ni = 0; ni < 4; ni++) {                    \
            int l = lane & 15;                                                \
            int rn = wn * 32 + ni * 8 + (l & 7);                              \
            int kb = ks * 32 + ((l & 8) ? 16 : 0);                            \
            uint32_t sw = (uint32_t)rn * 128 + (kb ^ ((rn & 7) << 4));        \
            uint32_t bh2[2], bl2[2];                                          \
            ldsm_x2(bh2, uBhi + sw);                                          \
            ldsm_x2(bl2, uBlo + sw);                                          \
            _Pragma("unroll") for (int mi = 0; mi < 4; mi++)                  \
                mma_bf16(acc[mi][ni], ah[mi], bh2);                           \
            _Pragma("unroll") for (int mi = 0; mi < 4; mi++)                  \
                mma_bf16(acc[mi][ni], ah[mi], bl2);                           \
            _Pragma("unroll") for (int mi = 0; mi < 4; mi++)                  \
                mma_bf16(acc[mi][ni], al[mi], bh2);                           \
        }                                                                     \
    }

#define SPLIT_STORE(av, r, cc)                                                \
    {                                                                         \
        uint2 h2, l2;                                                         \
        h2.x = pack_split((av).x, (av).y, l2.x);                              \
        h2.y = pack_split((av).z, (av).w, l2.y);                              \
        uint32_t off = (uint32_t)(r) * 128 + (((cc) * 2) ^ (((r) & 7) << 4)); \
        *(uint2*)(sAhi + off) = h2;                                           \
        *(uint2*)(sAlo + off) = l2;                                           \
    }

#define A_TRANS_BN(OUT, KB)                                                   \
    {                                                                         \
        const int cr = tid >> 4, cc = (tid & 15) * 4;                         \
        float4 sc = *(float4*)&sScale[(KB) + cc];                             \
        float4 sh = *(float4*)&sShift[(KB) + cc];                             \
        _Pragma("unroll") for (int ii = 0; ii < 8; ii++) {                    \
            const int r = cr + ii * 16;                                       \
            float4 av = *(const float4*)(sRAW + r * 256 + cc * 4);            \
            av.x = lky(fmaf(av.x, sc.x, sh.x));                               \
            av.y = lky(fmaf(av.y, sc.y, sh.y));                               \
            av.z = lky(fmaf(av.z, sc.z, sh.z));                               \
            av.w = lky(fmaf(av.w, sc.w, sh.w));                               \
            *(float4*)((OUT) + (size_t)(row0 + r) * HD + (KB) + cc) = av;     \
            SPLIT_STORE(av, r, cc);                                           \
        }                                                                     \
    }

#define A_TRANS_TP(OUT, LCP, NEP, KB)                                         \
    {                                                                         \
        const int cr = tid >> 4, cc = (tid & 15) * 4;                         \
        float4 sc = *(float4*)&sScale[(KB) + cc];                             \
        float4 sh = *(float4*)&sShift[(KB) + cc];                             \
        float4 wp = *(float4*)&sWP[(KB) + cc];                                \
        _Pragma("unroll") for (int ii = 0; ii < 8; ii++) {                    \
            const int r = cr + ii * 16;                                       \
            size_t gx = (size_t)(row0 + r) * HD + (KB) + cc;                  \
            float4 av = *(const float4*)(sRAW + r * 256 + cc * 4);            \
            av.x = lky(fmaf(av.x, sc.x, sh.x));                               \
            av.y = lky(fmaf(av.y, sc.y, sh.y));                               \
            av.z = lky(fmaf(av.z, sc.z, sh.z));                               \
            av.w = lky(fmaf(av.w, sc.w, sh.w));                               \
            *(float4*)((OUT) + gx) = av;                                      \
            float4 lv = *(const float4*)((LCP) + gx);                         \
            float4 nv = *(const float4*)((NEP) + gx);                         \
            pv[ii] = fmaf(av.x + lv.x + nv.x, wp.x, pv[ii]);                  \
            pv[ii] = fmaf(av.y + lv.y + nv.y, wp.y, pv[ii]);                  \
            pv[ii] = fmaf(av.z + lv.z + nv.z, wp.z, pv[ii]);                  \
            pv[ii] = fmaf(av.w + lv.w + nv.w, wp.w, pv[ii]);                  \
            SPLIT_STORE(av, r, cc);                                           \
        }                                                                     \
    }

// epilogue iteration: rr = global row, cb = global column (pair base)
#define EPI_BEGIN                                                             \
    _Pragma("unroll") for (int mi = 0; mi < 4; mi++) {                        \
        _Pragma("unroll") for (int h = 0; h < 2; h++) {                       \
            const int rr = row0 + wm * 64 + mi * 16 + (lane >> 2) + h * 8;    \
            _Pragma("unroll") for (int ni = 0; ni < 4; ni++) {                \
                const int cb = ncol0 + wn * 32 + ni * 8 + (lane & 3) * 2;     \
                float vx = acc[mi][ni][h * 2], vy = acc[mi][ni][h * 2 + 1];   \
                (void)cb;

#define EPI_END_STORE(OUT)                                                    \
                *(float2*)((OUT) + (size_t)rr * HD + cb) = make_float2(vx, vy); \
            } } }

#define EPI_END_ACC                                                           \
                acc[mi][ni][h * 2] = vx; acc[mi][ni][h * 2 + 1] = vy;         \
            } } }

#define STATS_DECL                                                            \
    float ssum[4][2], ssq[4][2];                                              \
    _Pragma("unroll") for (int i_ = 0; i_ < 4; i_++) {                        \
        ssum[i_][0] = ssum[i_][1] = 0.0f; ssq[i_][0] = ssq[i_][1] = 0.0f; }

#define STATS_ACC                                                             \
    ssum[ni][0] += vx; ssq[ni][0] += vx * vx;                                 \
    ssum[ni][1] += vy; ssq[ni][1] += vy * vy;

#define STATS_REDUCE(SIDX)                                                    \
    _Pragma("unroll") for (int ni = 0; ni < 4; ni++) {                        \
        _Pragma("unroll") for (int c2 = 0; c2 < 2; c2++) {                    \
            float s_ = ssum[ni][c2], q_ = ssq[ni][c2];                        \
            s_ += __shfl_xor_sync(~0u, s_, 4);  q_ += __shfl_xor_sync(~0u, q_, 4);  \
            s_ += __shfl_xor_sync(~0u, s_, 8);  q_ += __shfl_xor_sync(~0u, q_, 8);  \
            s_ += __shfl_xor_sync(~0u, s_, 16); q_ += __shfl_xor_sync(~0u, q_, 16); \
            if (lane < 4) {                                                   \
                int col = ncol0 + wn * 32 + ni * 8 + lane * 2 + c2;           \
                atomicAdd(&g_stats[(SIDX) * HD + col], s_);                   \
                atomicAdd(&g_stats[((SIDX) + 1) * HD + col], q_);             \
            } } }

#define BN_PREP(SIDX, G, B)                                                   \
    {                                                                         \
        float m_ = g_stats[(SIDX) * HD + tid] * (1.0f / (float)BD);           \
        float e2_ = g_stats[((SIDX) + 1) * HD + tid] * (1.0f / (float)BD);    \
        float rs_ = rsqrtf(e2_ - m_ * m_ + 1e-5f);                            \
        float sc_ = rs_ * (G)[tid];                                           \
        sScale[tid] = sc_;                                                    \
        sShift[tid] = (B)[tid] - m_ * sc_;                                    \
    }

#define BIAS4(DST, SRCP)                                                      \
    float2 DST[4];                                                            \
    _Pragma("unroll") for (int i_ = 0; i_ < 4; i_++)                          \
        DST[i_] = *(const float2*)((SRCP) + ncol0 + wn * 32 + i_ * 8 + (lane & 3) * 2);

// ---------------- prep kernels ----------------

__global__ void __launch_bounds__(NTH) k0_prep(
    const float* __restrict__ Wx, const float* __restrict__ bx,
    const float* __restrict__ Wi, const float* __restrict__ bi,
    const float* __restrict__ WC, const float* __restrict__ bC) {
    int h = threadIdx.x;
    if (blockIdx.x < HD) {
        __shared__ float sA[HD];
        sA[h] = Wx[blockIdx.x * HD + h];
        __syncthreads();
        float aI = 0.0f, aC = 0.0f;
#pragma unroll 4
        for (int k = 0; k < HD; k++) {
            float a = sA[k];
            aI = fmaf(a, Wi[k * HD + h], aI);
            aC = fmaf(a, WC[k * HD + h], aC);
        }
        g_WxWi[blockIdx.x * HD + h] = aI;
        g_WxWC[blockIdx.x * HD + h] = aC;
    } else {
        float aI = bi[h], aC = bC[h];
        for (int k = 0; k < HD; k++) {
            float a = bx[k];
            aI = fmaf(a, Wi[k * HD + h], aI);
            aC = fmaf(a, WC[k * HD + h], aC);
        }
        g_bxWi[h] = aI;
        g_bxWC[h] = aC;
#pragma unroll
        for (int s = 0; s < 6; s++) g_stats[s * HD + h] = 0.0f;
    }
}

// weights -> transposed [N][K] bf16 hi/lo, chunked by K=64, XOR-swizzled 128B rows
__global__ void __launch_bounds__(NTH) kW(
    const float* __restrict__ Wx, const float* __restrict__ Wh,
    const float* __restrict__ Wf, const float* __restrict__ WLC,
    const float* __restrict__ Wo) {
    int k = blockIdx.x, m = blockIdx.y, n = threadIdx.x;
    const float* src;
    switch (m) {
        case 0: src = Wx; break;
        case 1: src = Wh; break;
        case 2: src = Wf; break;
        case 3: src = g_WxWC; break;
        case 4: src = g_WxWi; break;
        case 5: src = WLC; break;
        default: src = Wo; break;
    }
    float val = src[k * HD + n];
    __nv_bfloat16 h = __float2bfloat16(val);
    __nv_bfloat16 l = __float2bfloat16(val - __bfloat162float(h));
    int chunk = k >> 6, kk = k & 63;
    uint32_t off = (uint32_t)chunk * 32768 + (uint32_t)n * 128 + ((kk * 2) ^ ((n & 7) << 4));
    *(__nv_bfloat16*)((char*)g_Wimg[m][0] + off) = h;
    *(__nv_bfloat16*)((char*)g_Wimg[m][1] + off) = l;
}

// activations X/pLC/pC -> bf16 hi/lo images, tiled (rowtile 128 x chunk 64)
// blocks of 8192 elems, 128B swizzled rows (identical formula to SPLIT_STORE).
__global__ void __launch_bounds__(NTH) kA(
    const float* __restrict__ X, const float* __restrict__ pLC,
    const float* __restrict__ pC) {
    int rt = blockIdx.x, m = blockIdx.y;
    const float* src = (m == 0) ? X : ((m == 1) ? pLC : pC);
    __nv_bfloat16* dh = g_Aimg[m][0];
    __nv_bfloat16* dl = g_Aimg[m][1];
    int tid = threadIdx.x;
    int r = tid >> 1;
    int kh = (tid & 1) * 32;
#pragma unroll
    for (int ch = 0; ch < 4; ch++) {
        const float* sp = src + ((size_t)(rt * 128 + r)) * HD + ch * 64 + kh;
        char* dbh = (char*)(dh + ((size_t)(rt * 4 + ch)) * 8192);
        char* dbl = (char*)(dl + ((size_t)(rt * 4 + ch)) * 8192);
#pragma unroll
        for (int q = 0; q < 8; q++) {
            float4 av = *(const float4*)(sp + q * 4);
            uint2 h2, l2;
            h2.x = pack_split(av.x, av.y, l2.x);
            h2.y = pack_split(av.z, av.w, l2.y);
            int kk = kh + q * 4;
            uint32_t off = (uint32_t)r * 128 + (uint32_t)((kk * 2) ^ ((r & 7) << 4));
            *(uint2*)(dbh + off) = h2;
            *(uint2*)(dbl + off) = l2;
        }
    }
}

// ---------------- lean pre-split MMA pipeline (k1a/k1b/k1c) ----------------
// per chunk: cp.async A(c+1)->A[(c+1)&1]; wait(1); sync; MMA(c); sync; cp.async B(c+1)

#define LEAN_LOOP(C, IMGSEL, MATSEL, POSTMMA)                                 \
    {                                                                         \
        { int im_ = IMGSEL(0); A2_CPASYNC(g_Aimg[im_][0], g_Aimg[im_][1], 0, 0); } \
        { int wm_ = MATSEL(0); B_CPASYNC(g_Wimg[wm_][0], g_Wimg[wm_][1], 0); }\
        _Pragma("unroll 1")                                                   \
        for (int c = 0; c < (C); c++) {                                       \
            if (c + 1 < (C)) {                                                \
                int im_ = IMGSEL(c + 1);                                      \
                A2_CPASYNC(g_Aimg[im_][0], g_Aimg[im_][1], (c + 1) & 3, (c + 1) & 1); \
                asm volatile("cp.async.wait_group 1;" ::: "memory");          \
            } else {                                                          \
                asm volatile("cp.async.wait_group 0;" ::: "memory");          \
            }                                                                 \
            __syncthreads();                                                  \
            COMPUTE_CHUNK((uint32_t)(c & 1) * 32768);                         \
            POSTMMA(c);                                                       \
            __syncthreads();                                                  \
            if (c + 1 < (C)) {                                                \
                int wm_ = MATSEL(c + 1);                                      \
                B_CPASYNC(g_Wimg[wm_][0], g_Wimg[wm_][1], (c + 1) & 3);       \
            }                                                                 \
        }                                                                     \
    }

#define NOPOST(c)

// ---------------- GEMM kernels ----------------

// k1a: LC_raw = X@Wx + pLC@Wh + (bx+bh) -> g_scr1; stats0 (8 chunks)
#define IMG_1A(c) (((c) < 4) ? 0 : 1)
#define MAT_1A(c) (((c) < 4) ? 0 : 1)
__global__ void __launch_bounds__(NTH, 2) k1a(
    const float* __restrict__ bx, const float* __restrict__ bh_) {
    GEMM_PROLOG;
    LEAN_LOOP(8, IMG_1A, MAT_1A, NOPOST);
    BIAS4(b1, bx); BIAS4(b2, bh_);
    STATS_DECL;
    EPI_BEGIN;
    vx += b1[ni].x + b2[ni].x;
    vy += b1[ni].y + b2[ni].y;
    STATS_ACC;
    EPI_END_STORE(g_scr1);
    STATS_REDUCE(0);
}

// k1b: base = sigmoid(pC@Wf+bf)*cell + X@WxWC + bxWC -> sec2 (mid-transform at c==3)
#define IMG_1B(c) (((c) < 4) ? 2 : 0)
#define MAT_1B(c) (((c) < 4) ? 2 : 3)
#define POST_1B(c)                                                            \
    if ((c) == 3) {                                                           \
        BIAS4(bfv, bf_);                                                      \
        EPI_BEGIN;                                                            \
        float2 cv = *(const float2*)(cell + (size_t)rr * HD + cb);            \
        vx = sigm(vx + bfv[ni].x) * cv.x;                                     \
        vy = sigm(vy + bfv[ni].y) * cv.y;                                     \
        EPI_END_ACC;                                                          \
    }
__global__ void __launch_bounds__(NTH, 2) k1b(
    const float* __restrict__ bf_, const float* __restrict__ cell, float* out) {
    GEMM_PROLOG;
    LEAN_LOOP(8, IMG_1B, MAT_1B, POST_1B);
    BIAS4(bb, g_bxWC);
    EPI_BEGIN;
    vx += bb[ni].x;
    vy += bb[ni].y;
    EPI_END_STORE(out);
}

// k1c: igate = sigmoid(X@WxWi + bxWi) -> sec3 (4 chunks)
#define IMG_1C(c) 0
#define MAT_1C(c) 4
__global__ void __launch_bounds__(NTH, 2) k1c(float* out) {
    GEMM_PROLOG;
    LEAN_LOOP(4, IMG_1C, MAT_1C, NOPOST);
    BIAS4(bb, g_bxWi);
    EPI_BEGIN;
    vx = sigm(vx + bb[ni].x);
    vy = sigm(vy + bb[ni].y);
    EPI_END_STORE(out);
}

// k2: LC_t = leaky(bn1(g_scr1)) -> sec0; NE_raw = LC_t@WLC + bLC -> g_scr2; stats2
__global__ void __launch_bounds__(NTH, 2) k2(
    float* out_lct, const float* __restrict__ bLC,
    const float* __restrict__ g1, const float* __restrict__ be1) {
    GEMM_PROLOG;
    BN_PREP(0, g1, be1);
    A_CPASYNC(g_scr1, 0);
#pragma unroll 1
    for (int c = 0; c < 4; c++) {
        PIPE_WAIT_SYNC;
        B_CPASYNC(g_Wimg[5][0], g_Wimg[5][1], c);
        A_TRANS_BN(out_lct, c * 64);
        PIPE_WAIT_SYNC;
        if (c < 3) A_CPASYNC(g_scr1, (c + 1) * 64);
        COMPUTE_CHUNK(OFF_AHI);
    }
    BIAS4(bb, bLC);
    STATS_DECL;
    EPI_BEGIN;
    vx += bb[ni].x;
    vy += bb[ni].y;
    STATS_ACC;
    EPI_END_STORE(g_scr2);
    STATS_REDUCE(2);
}

// k3: NE_t = leaky(bn2(g_scr2)) -> sec1; new_cell = base + ig*0.1*(NE_t@WLC+bLC) -> sec4; stats4
__global__ void __launch_bounds__(NTH, 2) k3(
    float* out_nc, float* out_net, const float* __restrict__ bLC,
    const float* __restrict__ base, const float* __restrict__ ig,
    const float* __restrict__ g2, const float* __restrict__ be2) {
    GEMM_PROLOG;
    BN_PREP(2, g2, be2);
    A_CPASYNC(g_scr2, 0);
#pragma unroll 1
    for (int c = 0; c < 4; c++) {
        PIPE_WAIT_SYNC;
        B_CPASYNC(g_Wimg[5][0], g_Wimg[5][1], c);
        A_TRANS_BN(out_net, c * 64);
        PIPE_WAIT_SYNC;
        if (c < 3) A_CPASYNC(g_scr2, (c + 1) * 64);
        COMPUTE_CHUNK(OFF_AHI);
    }
    BIAS4(bb, bLC);
    STATS_DECL;
    EPI_BEGIN;
    float2 bv = *(const float2*)(base + (size_t)rr * HD + cb);
    float2 iv = *(const float2*)(ig + (size_t)rr * HD + cb);
    vx = fmaf(iv.x * 0.1f, vx + bb[ni].x, bv.x);
    vy = fmaf(iv.y * 0.1f, vy + bb[ni].y, bv.y);
    STATS_ACC;
    EPI_END_STORE(out_nc);
    STATS_REDUCE(4);
}

// k4: C_t = leaky(bn3(sec4)) -> sec2; p = (LC_t+C_t+NE_t)@WP;
//     Pupil = sigmoid(C_t@Wo+bo)*(p+bP) -> sec3
__global__ void __launch_bounds__(NTH, 2) k4(
    const float* __restrict__ ncell, float* out_ct,
    const float* __restrict__ lct, const float* __restrict__ net,
    const float* __restrict__ bo, const float* __restrict__ WP,
    const float* __restrict__ bP, const float* __restrict__ g3,
    const float* __restrict__ be3, float* out_pupil) {
    GEMM_PROLOG;
    BN_PREP(4, g3, be3);
    float* sWP = (float*)(smem + OFF_WP);
    float* p_s = (float*)(smem + OFF_PS);
    sWP[tid] = WP[tid];
    if (tid < MT) p_s[tid] = 0.0f;
    float pv[8];
#pragma unroll
    for (int i = 0; i < 8; i++) pv[i] = 0.0f;
    A_CPASYNC(ncell, 0);
#pragma unroll 1
    for (int c = 0; c < 4; c++) {
        PIPE_WAIT_SYNC;
        B_CPASYNC(g_Wimg[6][0], g_Wimg[6][1], c);
        A_TRANS_TP(out_ct, lct, net, c * 64);
        PIPE_WAIT_SYNC;
        if (c < 3) A_CPASYNC(ncell, (c + 1) * 64);
        COMPUTE_CHUNK(OFF_AHI);
    }
    {
        const int crr = tid >> 4;
#pragma unroll
        for (int ii = 0; ii < 8; ii++) atomicAdd(&p_s[crr + ii * 16], pv[ii]);
    }
    __syncthreads();
    float bP0 = bP[0];
    BIAS4(bb, bo);
    EPI_BEGIN;
    float pr = p_s[rr - row0] + bP0;
    vx = sigm(vx + bb[ni].x) * pr;
    vy = sigm(vy + bb[ni].y) * pr;
    EPI_END_STORE(out_pupil);
}

// ---------------- launch ----------------

extern "C" void kernel_launch(void* const* d_in, const int* in_sizes, int n_in,
                              void* d_out, int out_size) {
    (void)in_sizes; (void)n_in; (void)out_size;
    const float* X    = (const float*)d_in[0];
    const float* pLC  = (const float*)d_in[1];
    const float* pC   = (const float*)d_in[2];
    const float* cell = (const float*)d_in[3];
    const float* Wx = (const float*)d_in[4];   const float* bx = (const float*)d_in[5];
    const float* Wh = (const float*)d_in[6];   const float* bh = (const float*)d_in[7];
    const float* WLC = (const float*)d_in[8];  const float* bLC = (const float*)d_in[9];
    const float* WC = (const float*)d_in[10];  const float* bC = (const float*)d_in[11];
    const float* WP = (const float*)d_in[12];  const float* bP = (const float*)d_in[13];
    const float* Wf = (const float*)d_in[14];  const float* bf = (const float*)d_in[15];
    const float* Wi = (const float*)d_in[16];  const float* bi = (const float*)d_in[17];
    const float* Wo = (const float*)d_in[18];  const float* bo = (const float*)d_in[19];
    const float* g1 = (const float*)d_in[20];  const float* be1 = (const float*)d_in[21];
    const float* g2 = (const float*)d_in[22];  const float* be2 = (const float*)d_in[23];
    const float* g3 = (const float*)d_in[24];  const float* be3 = (const float*)d_in[25];

    float* o = (float*)d_out;
    const size_t SEC = (size_t)BD * HD;
    float* sLC = o;            // LC_t   (written by k2)
    float* sNE = o + SEC;      // NE_t   (written by k3)
    float* sCT = o + 2 * SEC;  // C_t    (base until k3 consumes it; k4 writes C_t)
    float* sPU = o + 3 * SEC;  // Pupil  (igate until k3; k4 writes Pupil)
    float* sNC = o + 4 * SEC;  // new_cell (written by k3)

    // idempotent; called every time (no static guards per harness contract)
    cudaFuncSetAttribute(k1a, cudaFuncAttributeMaxDynamicSharedMemorySize, SMEM_REQ);
    cudaFuncSetAttribute(k1b, cudaFuncAttributeMaxDynamicSharedMemorySize, SMEM_REQ);
    cudaFuncSetAttribute(k1c, cudaFuncAttributeMaxDynamicSharedMemorySize, SMEM_REQ);
    cudaFuncSetAttribute(k2, cudaFuncAttributeMaxDynamicSharedMemorySize, SMEM_REQ);
    cudaFuncSetAttribute(k3, cudaFuncAttributeMaxDynamicSharedMemorySize, SMEM_REQ);
    cudaFuncSetAttribute(k4, cudaFuncAttributeMaxDynamicSharedMemorySize, SMEM_REQ);

    dim3 blk(NTH);
    dim3 grd(BD / MT, HD / NT);

    k0_prep<<<HD + 1, NTH>>>(Wx, bx, Wi, bi, WC, bC);
    kW<<<dim3(HD, 7), NTH>>>(Wx, Wh, Wf, WLC, Wo);
    kA<<<dim3(BD / MT, 3), NTH>>>(X, pLC, pC);
    k1a<<<grd, blk, SMEM_REQ>>>(bx, bh);
    k1b<<<grd, blk, SMEM_REQ>>>(bf, cell, sCT);
    k1c<<<grd, blk, SMEM_REQ>>>(sPU);
    k2<<<grd, blk, SMEM_REQ>>>(sLC, bLC, g1, be1);
    k3<<<grd, blk, SMEM_REQ>>>(sNC, sNE, bLC, sCT, sPU, g2, be2);
    k4<<<grd, blk, SMEM_REQ>>>(sNC, sCT, sLC, sNE, bo, WP, bP, g3, be3, sPU);
}

// round 17
// speedup vs baseline: 1.7900x; 1.7104x over previous
#include <cuda_runtime.h>
#include <cuda_fp16.h>
#include <math.h>
#include <stdint.h>

// LCNECortexLSTM B=65536, D=H=256 — mma.sync (HMMA fp16) split-precision pipeline.
// R17 = R14 structure (K=64 chunks, cp.async staged raw A + B, 2 CTAs/SM) with a
// cheaper numeric scheme: A split into fp16 hi+lo (22-bit effective), B rounded
// to a SINGLE fp16. D = Ahi@Bhi + Alo@Bhi (2 MMA terms instead of 3).
// Per-GEMM error ~2.8e-4 (B rounding), chain ~4e-4 < 1e-3 threshold.

#define BD 65536
#define HD 256
#define MT 128
#define NT 128
#define NTH 256

#define OFF_RAW 0
#define OFF_AHI 32768
#define OFF_ALO 49152
#define OFF_BHI 65536
#define OFF_SCALE 98304
#define OFF_SHIFT 99328
#define OFF_WP 100352
#define OFF_PS 101376
#define SMEM_REQ 102912

// weight images: fp16 (hi only), transposed [N][K], chunked 4x(256 rows x 64 k),
// 128B rows with XOR-16B swizzle. mats: 0=Wx 1=Wh 2=Wf 3=WxWC 4=WxWi 5=WLC 6=Wo
__device__ unsigned short g_Wimg[7][HD * HD];
__device__ float g_WxWi[HD * HD];
__device__ float g_WxWC[HD * HD];
__device__ float g_bxWi[HD];
__device__ float g_bxWC[HD];
__device__ float g_stats[6 * HD];
__device__ float g_scr1[(size_t)BD * HD];  // LC_raw
__device__ float g_scr2[(size_t)BD * HD];  // NE_raw

__device__ __forceinline__ float sigm(float x) { return 1.0f / (1.0f + expf(-x)); }
__device__ __forceinline__ float lky(float x) { return x > 0.0f ? x : 0.1f * x; }

__device__ __forceinline__ uint32_t smem_to_u32(const void* p) {
    uint32_t a;
    asm("{ .reg .u64 t; cvta.to.shared.u64 t, %1; cvt.u32.u64 %0, t; }" : "=r"(a) : "l"(p));
    return a;
}

__device__ __forceinline__ void ldsm_x4(uint32_t* r, uint32_t addr) {
    asm volatile("ldmatrix.sync.aligned.m8n8.x4.shared.b16 {%0,%1,%2,%3}, [%4];"
        : "=r"(r[0]), "=r"(r[1]), "=r"(r[2]), "=r"(r[3]) : "r"(addr));
}
__device__ __forceinline__ void ldsm_x2(uint32_t* r, uint32_t addr) {
    asm volatile("ldmatrix.sync.aligned.m8n8.x2.shared.b16 {%0,%1}, [%2];"
        : "=r"(r[0]), "=r"(r[1]) : "r"(addr));
}
__device__ __forceinline__ void mma_f16(float* c, const uint32_t* a, const uint32_t* b) {
    asm("mma.sync.aligned.m16n8k16.row.col.f32.f16.f16.f32 "
        "{%0,%1,%2,%3}, {%4,%5,%6,%7}, {%8,%9}, {%0,%1,%2,%3};"
        : "+f"(c[0]), "+f"(c[1]), "+f"(c[2]), "+f"(c[3])
        : "r"(a[0]), "r"(a[1]), "r"(a[2]), "r"(a[3]), "r"(b[0]), "r"(b[1]));
}
__device__ __forceinline__ void cp16(uint32_t dst, const void* src) {
    asm volatile("cp.async.cg.shared.global [%0], [%1], 16;" :: "r"(dst), "l"(src));
}

// fp16 split: hi = rn(a), lo = rn(a - hi). Returns packed hi pair, writes lo pair.
__device__ __forceinline__ uint32_t pack_split(float a, float b, uint32_t& lo) {
    __half2 h = __floats2half2_rn(a, b);
    __half2 l = __floats2half2_rn(a - __half2float(__low2half(h)),
                                  b - __half2float(__high2half(h)));
    lo = *reinterpret_cast<uint32_t*>(&l);
    return *reinterpret_cast<uint32_t*>(&h);
}

// ---------------- kernel body macros ----------------

#define GEMM_PROLOG                                                           \
    extern __shared__ char dsm_[];                                            \
    char* smem = (char*)(((uintptr_t)dsm_ + 1023) & ~(uintptr_t)1023);        \
    const int tid = threadIdx.x, wid = tid >> 5, lane = tid & 31;             \
    const int wm = wid & 1, wn = wid >> 1;                                    \
    const int row0 = blockIdx.x * MT;                                         \
    const int ncol0 = blockIdx.y * NT;                                        \
    const uint32_t su = smem_to_u32(smem);                                    \
    char* sRAW = smem + OFF_RAW;                                              \
    char* sAhi = smem + OFF_AHI; char* sAlo = smem + OFF_ALO;                 \
    const uint32_t uRAW = su + OFF_RAW;                                       \
    const uint32_t uAhi = su + OFF_AHI, uAlo = su + OFF_ALO;                  \
    const uint32_t uBhi = su + OFF_BHI;                                       \
    float* sScale = (float*)(smem + OFF_SCALE);                               \
    float* sShift = (float*)(smem + OFF_SHIFT);                               \
    (void)sScale; (void)sShift; (void)sRAW; (void)sAlo;                       \
    float acc[4][4][4];                                                       \
    _Pragma("unroll") for (int i_ = 0; i_ < 4; i_++)                          \
        _Pragma("unroll") for (int j_ = 0; j_ < 4; j_++)                      \
            _Pragma("unroll") for (int q_ = 0; q_ < 4; q_++)                  \
                acc[i_][j_][q_] = 0.0f;

// cp.async one raw fp32 A chunk (128 rows x 64 cols) into sRAW; commits a group.
#define A_CPASYNC(SRC, KB)                                                    \
    {                                                                         \
        const int pr_ = tid >> 4, ps_ = (tid & 15) * 16;                      \
        _Pragma("unroll") for (int ii = 0; ii < 8; ii++) {                    \
            int r_ = pr_ + ii * 16;                                           \
            cp16(uRAW + (uint32_t)r_ * 256 + ps_,                             \
                 (const char*)((SRC) + (size_t)(row0 + r_) * HD + (KB)) + ps_); \
        }                                                                     \
        asm volatile("cp.async.commit_group;" ::: "memory");                  \
    }

// cp.async one pre-swizzled fp16 B chunk (16KB); commits a group.
#define B_CPASYNC(WIMG, CH)                                                   \
    {                                                                         \
        const char* bh_ = (const char*)((WIMG) + (CH) * 16384 + ncol0 * 64);  \
        _Pragma("unroll") for (int i = 0; i < 4; i++) {                       \
            uint32_t o_ = (uint32_t)(i * NTH + tid) * 16;                     \
            cp16(uBhi + o_, bh_ + o_);                                        \
        }                                                                     \
        asm volatile("cp.async.commit_group;" ::: "memory");                  \
    }

#define PIPE_WAIT_SYNC                                                        \
    asm volatile("cp.async.wait_group 0;" ::: "memory");                      \
    __syncthreads();

// 2-term fp16 MMA: acc += Ahi*Bhi; acc += Alo*Bhi.
#define COMPUTE_CHUNK                                                         \
    _Pragma("unroll") for (int ks = 0; ks < 4; ks++) {                        \
        uint32_t ah[4][4], al[4][4];                                          \
        _Pragma("unroll") for (int mi = 0; mi < 4; mi++) {                    \
            int r = wm * 64 + mi * 16 + (lane & 15);                          \
            int kb = ks * 32 + ((lane & 16) ? 16 : 0);                        \
            uint32_t sw = (uint32_t)r * 128 + (kb ^ ((r & 7) << 4));          \
            ldsm_x4(ah[mi], uAhi + sw);                                       \
            ldsm_x4(al[mi], uAlo + sw);                                       \
        }                                                                     \
        _Pragma("unroll") for (int ni = 0; ni < 4; ni++) {                    \
            int l = lane & 15;                                                \
            int rn = wn * 32 + ni * 8 + (l & 7);                              \
            int kb = ks * 32 + ((l & 8) ? 16 : 0);                            \
            uint32_t sw = (uint32_t)rn * 128 + (kb ^ ((rn & 7) << 4));        \
            uint32_t bh2[2];                                                  \
            ldsm_x2(bh2, uBhi + sw);                                          \
            _Pragma("unroll") for (int mi = 0; mi < 4; mi++)                  \
                mma_f16(acc[mi][ni], ah[mi], bh2);                            \
            _Pragma("unroll") for (int mi = 0; mi < 4; mi++)                  \
                mma_f16(acc[mi][ni], al[mi], bh2);                            \
        }                                                                     \
    }

#define SPLIT_STORE(av, r, cc)                                                \
    {                                                                         \
        uint2 h2, l2;                                                         \
        h2.x = pack_split((av).x, (av).y, l2.x);                              \
        h2.y = pack_split((av).z, (av).w, l2.y);                              \
        uint32_t off = (uint32_t)(r) * 128 + (((cc) * 2) ^ (((r) & 7) << 4)); \
        *(uint2*)(sAhi + off) = h2;                                           \
        *(uint2*)(sAlo + off) = l2;                                           \
    }

// transforms read the raw chunk from SMEM (cp.async-staged)
#define A_TRANS_PLAIN                                                         \
    {                                                                         \
        const int cr = tid >> 4, cc = (tid & 15) * 4;                         \
        _Pragma("unroll") for (int ii = 0; ii < 8; ii++) {                    \
            const int r = cr + ii * 16;                                       \
            float4 av = *(const float4*)(sRAW + r * 256 + cc * 4);            \
            SPLIT_STORE(av, r, cc);                                           \
        }                                                                     \
    }

#define A_TRANS_BN(OUT, KB)                                                   \
    {                                                                         \
        const int cr = tid >> 4, cc = (tid & 15) * 4;                         \
        float4 sc = *(float4*)&sScale[(KB) + cc];                             \
        float4 sh = *(float4*)&sShift[(KB) + cc];                             \
        _Pragma("unroll") for (int ii = 0; ii < 8; ii++) {                    \
            const int r = cr + ii * 16;                                       \
            float4 av = *(const float4*)(sRAW + r * 256 + cc * 4);            \
            av.x = lky(fmaf(av.x, sc.x, sh.x));                               \
            av.y = lky(fmaf(av.y, sc.y, sh.y));                               \
            av.z = lky(fmaf(av.z, sc.z, sh.z));                               \
            av.w = lky(fmaf(av.w, sc.w, sh.w));                               \
            *(float4*)((OUT) + (size_t)(row0 + r) * HD + (KB) + cc) = av;     \
            SPLIT_STORE(av, r, cc);                                           \
        }                                                                     \
    }

#define A_TRANS_TP(OUT, LCP, NEP, KB)                                         \
    {                                                                         \
        const int cr = tid >> 4, cc = (tid & 15) * 4;                         \
        float4 sc = *(float4*)&sScale[(KB) + cc];                             \
        float4 sh = *(float4*)&sShift[(KB) + cc];                             \
        float4 wp = *(float4*)&sWP[(KB) + cc];                                \
        _Pragma("unroll") for (int ii = 0; ii < 8; ii++) {                    \
            const int r = cr + ii * 16;                                       \
            size_t gx = (size_t)(row0 + r) * HD + (KB) + cc;                  \
            float4 av = *(const float4*)(sRAW + r * 256 + cc * 4);            \
            av.x = lky(fmaf(av.x, sc.x, sh.x));                               \
            av.y = lky(fmaf(av.y, sc.y, sh.y));                               \
            av.z = lky(fmaf(av.z, sc.z, sh.z));                               \
            av.w = lky(fmaf(av.w, sc.w, sh.w));                               \
            *(float4*)((OUT) + gx) = av;                                      \
            float4 lv = *(const float4*)((LCP) + gx);                         \
            float4 nv = *(const float4*)((NEP) + gx);                         \
            pv[ii] = fmaf(av.x + lv.x + nv.x, wp.x, pv[ii]);                  \
            pv[ii] = fmaf(av.y + lv.y + nv.y, wp.y, pv[ii]);                  \
            pv[ii] = fmaf(av.z + lv.z + nv.z, wp.z, pv[ii]);                  \
            pv[ii] = fmaf(av.w + lv.w + nv.w, wp.w, pv[ii]);                  \
            SPLIT_STORE(av, r, cc);                                           \
        }                                                                     \
    }

// epilogue iteration: rr = global row, cb = global column (pair base)
#define EPI_BEGIN                                                             \
    _Pragma("unroll") for (int mi = 0; mi < 4; mi++) {                        \
        _Pragma("unroll") for (int h = 0; h < 2; h++) {                       \
            const int rr = row0 + wm * 64 + mi * 16 + (lane >> 2) + h * 8;    \
            _Pragma("unroll") for (int ni = 0; ni < 4; ni++) {                \
                const int cb = ncol0 + wn * 32 + ni * 8 + (lane & 3) * 2;     \
                float vx = acc[mi][ni][h * 2], vy = acc[mi][ni][h * 2 + 1];   \
                (void)cb;

#define EPI_END_STORE(OUT)                                                    \
                *(float2*)((OUT) + (size_t)rr * HD + cb) = make_float2(vx, vy); \
            } } }

#define EPI_END_ACC                                                           \
                acc[mi][ni][h * 2] = vx; acc[mi][ni][h * 2 + 1] = vy;         \
            } } }

#define STATS_DECL                                                            \
    float ssum[4][2], ssq[4][2];                                              \
    _Pragma("unroll") for (int i_ = 0; i_ < 4; i_++) {                        \
        ssum[i_][0] = ssum[i_][1] = 0.0f; ssq[i_][0] = ssq[i_][1] = 0.0f; }

#define STATS_ACC                                                             \
    ssum[ni][0] += vx; ssq[ni][0] += vx * vx;                                 \
    ssum[ni][1] += vy; ssq[ni][1] += vy * vy;

#define STATS_REDUCE(SIDX)                                                    \
    _Pragma("unroll") for (int ni = 0; ni < 4; ni++) {                        \
        _Pragma("unroll") for (int c2 = 0; c2 < 2; c2++) {                    \
            float s_ = ssum[ni][c2], q_ = ssq[ni][c2];                        \
            s_ += __shfl_xor_sync(~0u, s_, 4);  q_ += __shfl_xor_sync(~0u, q_, 4);  \
            s_ += __shfl_xor_sync(~0u, s_, 8);  q_ += __shfl_xor_sync(~0u, q_, 8);  \
            s_ += __shfl_xor_sync(~0u, s_, 16); q_ += __shfl_xor_sync(~0u, q_, 16); \
            if (lane < 4) {                                                   \
                int col = ncol0 + wn * 32 + ni * 8 + lane * 2 + c2;           \
                atomicAdd(&g_stats[(SIDX) * HD + col], s_);                   \
                atomicAdd(&g_stats[((SIDX) + 1) * HD + col], q_);             \
            } } }

#define BN_PREP(SIDX, G, B)                                                   \
    {                                                                         \
        float m_ = g_stats[(SIDX) * HD + tid] * (1.0f / (float)BD);           \
        float e2_ = g_stats[((SIDX) + 1) * HD + tid] * (1.0f / (float)BD);    \
        float rs_ = rsqrtf(e2_ - m_ * m_ + 1e-5f);                            \
        float sc_ = rs_ * (G)[tid];                                           \
        sScale[tid] = sc_;                                                    \
        sShift[tid] = (B)[tid] - m_ * sc_;                                    \
    }

#define BIAS4(DST, SRCP)                                                      \
    float2 DST[4];                                                            \
    _Pragma("unroll") for (int i_ = 0; i_ < 4; i_++)                          \
        DST[i_] = *(const float2*)((SRCP) + ncol0 + wn * 32 + i_ * 8 + (lane & 3) * 2);

// ---------------- prep kernels ----------------

__global__ void __launch_bounds__(NTH) k0_prep(
    const float* __restrict__ Wx, const float* __restrict__ bx,
    const float* __restrict__ Wi, const float* __restrict__ bi,
    const float* __restrict__ WC, const float* __restrict__ bC) {
    int h = threadIdx.x;
    if (blockIdx.x < HD) {
        __shared__ float sA[HD];
        sA[h] = Wx[blockIdx.x * HD + h];
        __syncthreads();
        float aI = 0.0f, aC = 0.0f;
#pragma unroll 4
        for (int k = 0; k < HD; k++) {
            float a = sA[k];
            aI = fmaf(a, Wi[k * HD + h], aI);
            aC = fmaf(a, WC[k * HD + h], aC);
        }
        g_WxWi[blockIdx.x * HD + h] = aI;
        g_WxWC[blockIdx.x * HD + h] = aC;
    } else {
        float aI = bi[h], aC = bC[h];
        for (int k = 0; k < HD; k++) {
            float a = bx[k];
            aI = fmaf(a, Wi[k * HD + h], aI);
            aC = fmaf(a, WC[k * HD + h], aC);
        }
        g_bxWi[h] = aI;
        g_bxWC[h] = aC;
#pragma unroll
        for (int s = 0; s < 6; s++) g_stats[s * HD + h] = 0.0f;
    }
}

// weights -> transposed [N][K] fp16, chunked by K=64, XOR-swizzled 128B rows
__global__ void __launch_bounds__(NTH) kW(
    const float* __restrict__ Wx, const float* __restrict__ Wh,
    const float* __restrict__ Wf, const float* __restrict__ WLC,
    const float* __restrict__ Wo) {
    int k = blockIdx.x, m = blockIdx.y, n = threadIdx.x;
    const float* src;
    switch (m) {
        case 0: src = Wx; break;
        case 1: src = Wh; break;
        case 2: src = Wf; break;
        case 3: src = g_WxWC; break;
        case 4: src = g_WxWi; break;
        case 5: src = WLC; break;
        default: src = Wo; break;
    }
    float val = src[k * HD + n];
    __half h = __float2half_rn(val);
    int chunk = k >> 6, kk = k & 63;
    uint32_t off = (uint32_t)chunk * 32768 + (uint32_t)n * 128 + ((kk * 2) ^ ((n & 7) << 4));
    *(unsigned short*)((char*)g_Wimg[m] + off) = *reinterpret_cast<unsigned short*>(&h);
}

// ---------------- GEMM kernels ----------------

// k1a: LC_raw = X@Wx + pLC@Wh + (bx+bh) -> g_scr1; stats0
__global__ void __launch_bounds__(NTH, 2) k1a(
    const float* __restrict__ X, const float* __restrict__ pLC,
    const float* __restrict__ bx, const float* __restrict__ bh_) {
    GEMM_PROLOG;
    A_CPASYNC(X, 0);
#pragma unroll 1
    for (int c = 0; c < 8; c++) {
        PIPE_WAIT_SYNC;  // rawA_c ready
        int mat = (c < 4) ? 0 : 1;
        B_CPASYNC(g_Wimg[mat], c & 3);
        A_TRANS_PLAIN;
        PIPE_WAIT_SYNC;  // B ready; raw buffer free
        if (c < 7) {
            const float* nsrc = (c + 1 < 4) ? X : pLC;
            A_CPASYNC(nsrc, ((c + 1) & 3) * 64);
        }
        COMPUTE_CHUNK;
    }
    BIAS4(b1, bx); BIAS4(b2, bh_);
    STATS_DECL;
    EPI_BEGIN;
    vx += b1[ni].x + b2[ni].x;
    vy += b1[ni].y + b2[ni].y;
    STATS_ACC;
    EPI_END_STORE(g_scr1);
    STATS_REDUCE(0);
}

// k1b: base = sigmoid(pC@Wf+bf)*cell + X@WxWC + bxWC -> sec2 (mid-transform at c==3)
__global__ void __launch_bounds__(NTH, 2) k1b(
    const float* __restrict__ pC, const float* __restrict__ X,
    const float* __restrict__ bf_, const float* __restrict__ cell, float* out) {
    GEMM_PROLOG;
    A_CPASYNC(pC, 0);
#pragma unroll 1
    for (int c = 0; c < 8; c++) {
        PIPE_WAIT_SYNC;
        int mat = (c < 4) ? 2 : 3;
        B_CPASYNC(g_Wimg[mat], c & 3);
        A_TRANS_PLAIN;
        PIPE_WAIT_SYNC;
        if (c < 7) {
            const float* nsrc = (c + 1 < 4) ? pC : X;
            A_CPASYNC(nsrc, ((c + 1) & 3) * 64);
        }
        COMPUTE_CHUNK;
        if (c == 3) {
            BIAS4(bfv, bf_);
            EPI_BEGIN;
            float2 cv = *(const float2*)(cell + (size_t)rr * HD + cb);
            vx = sigm(vx + bfv[ni].x) * cv.x;
            vy = sigm(vy + bfv[ni].y) * cv.y;
            EPI_END_ACC;
        }
    }
    BIAS4(bb, g_bxWC);
    EPI_BEGIN;
    vx += bb[ni].x;
    vy += bb[ni].y;
    EPI_END_STORE(out);
}

// k1c: igate = sigmoid(X@WxWi + bxWi) -> sec3
__global__ void __launch_bounds__(NTH, 2) k1c(const float* __restrict__ X, float* out) {
    GEMM_PROLOG;
    A_CPASYNC(X, 0);
#pragma unroll 1
    for (int c = 0; c < 4; c++) {
        PIPE_WAIT_SYNC;
        B_CPASYNC(g_Wimg[4], c);
        A_TRANS_PLAIN;
        PIPE_WAIT_SYNC;
        if (c < 3) A_CPASYNC(X, (c + 1) * 64);
        COMPUTE_CHUNK;
    }
    BIAS4(bb, g_bxWi);
    EPI_BEGIN;
    vx = sigm(vx + bb[ni].x);
    vy = sigm(vy + bb[ni].y);
    EPI_END_STORE(out);
}

// k2: LC_t = leaky(bn1(g_scr1)) -> sec0; NE_raw = LC_t@WLC + bLC -> g_scr2; stats2
__global__ void __launch_bounds__(NTH, 2) k2(
    float* out_lct, const float* __restrict__ bLC,
    const float* __restrict__ g1, const float* __restrict__ be1) {
    GEMM_PROLOG;
    BN_PREP(0, g1, be1);
    A_CPASYNC(g_scr1, 0);
#pragma unroll 1
    for (int c = 0; c < 4; c++) {
        PIPE_WAIT_SYNC;
        B_CPASYNC(g_Wimg[5], c);
        A_TRANS_BN(out_lct, c * 64);
        PIPE_WAIT_SYNC;
        if (c < 3) A_CPASYNC(g_scr1, (c + 1) * 64);
        COMPUTE_CHUNK;
    }
    BIAS4(bb, bLC);
    STATS_DECL;
    EPI_BEGIN;
    vx += bb[ni].x;
    vy += bb[ni].y;
    STATS_ACC;
    EPI_END_STORE(g_scr2);
    STATS_REDUCE(2);
}

// k3: NE_t = leaky(bn2(g_scr2)) -> sec1; new_cell = base + ig*0.1*(NE_t@WLC+bLC) -> sec4; stats4
__global__ void __launch_bounds__(NTH, 2) k3(
    float* out_nc, float* out_net, const float* __restrict__ bLC,
    const float* __restrict__ base, const float* __restrict__ ig,
    const float* __restrict__ g2, const float* __restrict__ be2) {
    GEMM_PROLOG;
    BN_PREP(2, g2, be2);
    A_CPASYNC(g_scr2, 0);
#pragma unroll 1
    for (int c = 0; c < 4; c++) {
        PIPE_WAIT_SYNC;
        B_CPASYNC(g_Wimg[5], c);
        A_TRANS_BN(out_net, c * 64);
        PIPE_WAIT_SYNC;
        if (c < 3) A_CPASYNC(g_scr2, (c + 1) * 64);
        COMPUTE_CHUNK;
    }
    BIAS4(bb, bLC);
    STATS_DECL;
    EPI_BEGIN;
    float2 bv = *(const float2*)(base + (size_t)rr * HD + cb);
    float2 iv = *(const float2*)(ig + (size_t)rr * HD + cb);
    vx = fmaf(iv.x * 0.1f, vx + bb[ni].x, bv.x);
    vy = fmaf(iv.y * 0.1f, vy + bb[ni].y, bv.y);
    STATS_ACC;
    EPI_END_STORE(out_nc);
    STATS_REDUCE(4);
}

// k4: C_t = leaky(bn3(sec4)) -> sec2; p = (LC_t+C_t+NE_t)@WP;
//     Pupil = sigmoid(C_t@Wo+bo)*(p+bP) -> sec3
__global__ void __launch_bounds__(NTH, 2) k4(
    const float* __restrict__ ncell, float* out_ct,
    const float* __restrict__ lct, const float* __restrict__ net,
    const float* __restrict__ bo, const float* __restrict__ WP,
    const float* __restrict__ bP, const float* __restrict__ g3,
    const float* __restrict__ be3, float* out_pupil) {
    GEMM_PROLOG;
    BN_PREP(4, g3, be3);
    float* sWP = (float*)(smem + OFF_WP);
    float* p_s = (float*)(smem + OFF_PS);
    sWP[tid] = WP[tid];
    if (tid < MT) p_s[tid] = 0.0f;
    float pv[8];
#pragma unroll
    for (int i = 0; i < 8; i++) pv[i] = 0.0f;
    A_CPASYNC(ncell, 0);
#pragma unroll 1
    for (int c = 0; c < 4; c++) {
        PIPE_WAIT_SYNC;
        B_CPASYNC(g_Wimg[6], c);
        A_TRANS_TP(out_ct, lct, net, c * 64);
        PIPE_WAIT_SYNC;
        if (c < 3) A_CPASYNC(ncell, (c + 1) * 64);
        COMPUTE_CHUNK;
    }
    {
        const int crr = tid >> 4;
#pragma unroll
        for (int ii = 0; ii < 8; ii++) atomicAdd(&p_s[crr + ii * 16], pv[ii]);
    }
    __syncthreads();
    float bP0 = bP[0];
    BIAS4(bb, bo);
    EPI_BEGIN;
    float pr = p_s[rr - row0] + bP0;
    vx = sigm(vx + bb[ni].x) * pr;
    vy = sigm(vy + bb[ni].y) * pr;
    EPI_END_STORE(out_pupil);
}

// ---------------- launch ----------------

extern "C" void kernel_launch(void* const* d_in, const int* in_sizes, int n_in,
                              void* d_out, int out_size) {
    (void)in_sizes; (void)n_in; (void)out_size;
    const float* X    = (const float*)d_in[0];
    const float* pLC  = (const float*)d_in[1];
    const float* pC   = (const float*)d_in[2];
    const float* cell = (const float*)d_in[3];
    const float* Wx = (const float*)d_in[4];   const float* bx = (const float*)d_in[5];
    const float* Wh = (const float*)d_in[6];   const float* bh = (const float*)d_in[7];
    const float* WLC = (const float*)d_in[8];  const float* bLC = (const float*)d_in[9];
    const float* WC = (const float*)d_in[10];  const float* bC = (const float*)d_in[11];
    const float* WP = (const float*)d_in[12];  const float* bP = (const float*)d_in[13];
    const float* Wf = (const float*)d_in[14];  const float* bf = (const float*)d_in[15];
    const float* Wi = (const float*)d_in[16];  const float* bi = (const float*)d_in[17];
    const float* Wo = (const float*)d_in[18];  const float* bo = (const float*)d_in[19];
    const float* g1 = (const float*)d_in[20];  const float* be1 = (const float*)d_in[21];
    const float* g2 = (const float*)d_in[22];  const float* be2 = (const float*)d_in[23];
    const float* g3 = (const float*)d_in[24];  const float* be3 = (const float*)d_in[25];

    float* o = (float*)d_out;
    const size_t SEC = (size_t)BD * HD;
    float* sLC = o;            // LC_t   (written by k2)
    float* sNE = o + SEC;      // NE_t   (written by k3)
    float* sCT = o + 2 * SEC;  // C_t    (base until k3 consumes it; k4 writes C_t)
    float* sPU = o + 3 * SEC;  // Pupil  (igate until k3; k4 writes Pupil)
    float* sNC = o + 4 * SEC;  // new_cell (written by k3)

    // idempotent; called every time (no static guards per harness contract)
    cudaFuncSetAttribute(k1a, cudaFuncAttributeMaxDynamicSharedMemorySize, SMEM_REQ);
    cudaFuncSetAttribute(k1b, cudaFuncAttributeMaxDynamicSharedMemorySize, SMEM_REQ);
    cudaFuncSetAttribute(k1c, cudaFuncAttributeMaxDynamicSharedMemorySize, SMEM_REQ);
    cudaFuncSetAttribute(k2, cudaFuncAttributeMaxDynamicSharedMemorySize, SMEM_REQ);
    cudaFuncSetAttribute(k3, cudaFuncAttributeMaxDynamicSharedMemorySize, SMEM_REQ);
    cudaFuncSetAttribute(k4, cudaFuncAttributeMaxDynamicSharedMemorySize, SMEM_REQ);

    dim3 blk(NTH);
    dim3 grd(BD / MT, HD / NT);

    k0_prep<<<HD + 1, NTH>>>(Wx, bx, Wi, bi, WC, bC);
    kW<<<dim3(HD, 7), NTH>>>(Wx, Wh, Wf, WLC, Wo);
    k1a<<<grd, blk, SMEM_REQ>>>(X, pLC, bx, bh);
    k1b<<<grd, blk, SMEM_REQ>>>(pC, X, bf, cell, sCT);
    k1c<<<grd, blk, SMEM_REQ>>>(X, sPU);
    k2<<<grd, blk, SMEM_REQ>>>(sLC, bLC, g1, be1);
    k3<<<grd, blk, SMEM_REQ>>>(sNC, sNE, bLC, sCT, sPU, g2, be2);
    k4<<<grd, blk, SMEM_REQ>>>(sNC, sCT, sLC, sNE, bo, WP, bP, g3, be3, sPU);
}